// round 5
// baseline (speedup 1.0000x reference)
#include <cuda_runtime.h>
#include <cuda_bf16.h>
#include <cuda_fp8.h>

// Problem constants
#define M_OUT   125000
#define KNB     8
#define CIN     96
#define COUT    192
#define BM      64
#define NCHUNK  24                        // K chunks of 32 (768 total)
#define NBLK    1954                      // ceil(125000/64)
#define BN_EPS  1e-5f
#define SBF     20                        // bf16 smem row stride (words)
#define S8      12                        // fp8 smem row stride (words): conflict-free

// Shared-memory pool offsets (32-bit words)
#define O_ABF   0                         // A bf16-hi pairs   [64][20]
#define O_A8H   (BM * SBF)                // A e4m3 hi         [64][12]
#define O_A8L   (O_A8H + BM * S8)
#define O_BBF   (O_A8L + BM * S8)         // B bf16-hi pairs   [192][20]
#define O_B8H   (O_BBF + COUT * SBF)      // B e4m3 hi         [192][12]
#define O_B8L   (O_B8H + COUT * S8)       // B e4m3 lo*256
#define O_SROW  (O_B8L + COUT * S8)
#define POOLW   (O_SROW + BM * KNB)       // 11776 words = 47104 B

// Deterministic scratch
__device__ float g_psum[COUT * NBLK];
__device__ float g_psq [COUT * NBLK];
__device__ float g_scale[COUT];
__device__ float g_shift[COUT];
__device__ int   g_is64;
// Pre-packed weights per chunk t: bf16-hi pairs, e4m3 hi, e4m3 lo*256
__device__ __align__(16) unsigned g_wbf[NCHUNK * COUT * 16];
__device__ __align__(16) unsigned g_w8h[NCHUNK * COUT * 8];
__device__ __align__(16) unsigned g_w8l[NCHUNK * COUT * 8];

// ---------------------------------------------------------------------------
#define HMMA(d, a0, a1, a2, a3, b0, b1)                                        \
    asm volatile(                                                              \
        "mma.sync.aligned.m16n8k16.row.col.f32.bf16.bf16.f32 "                 \
        "{%0,%1,%2,%3}, {%4,%5,%6,%7}, {%8,%9}, {%0,%1,%2,%3};"                \
        : "+f"((d)[0]), "+f"((d)[1]), "+f"((d)[2]), "+f"((d)[3])               \
        : "r"(a0), "r"(a1), "r"(a2), "r"(a3), "r"(b0), "r"(b1))

#define QMMA(d, a0, a1, a2, a3, b0, b1)                                        \
    asm volatile(                                                              \
        "mma.sync.aligned.m16n8k32.row.col.f32.e4m3.e4m3.f32 "                 \
        "{%0,%1,%2,%3}, {%4,%5,%6,%7}, {%8,%9}, {%0,%1,%2,%3};"                \
        : "+f"((d)[0]), "+f"((d)[1]), "+f"((d)[2]), "+f"((d)[3])               \
        : "r"(a0), "r"(a1), "r"(a2), "r"(a3), "r"(b0), "r"(b1))

__device__ __forceinline__ unsigned pack_e4m3(float a, float b, float c, float d)
{
    unsigned b0 = __nv_cvt_float_to_fp8(a, __NV_SATFINITE, __NV_E4M3);
    unsigned b1 = __nv_cvt_float_to_fp8(b, __NV_SATFINITE, __NV_E4M3);
    unsigned b2 = __nv_cvt_float_to_fp8(c, __NV_SATFINITE, __NV_E4M3);
    unsigned b3 = __nv_cvt_float_to_fp8(d, __NV_SATFINITE, __NV_E4M3);
    return b0 | (b1 << 8) | (b2 << 16) | (b3 << 24);
}

// ---------------------------------------------------------------------------
__global__ void noop_kernel() {}

__global__ void detect_kernel(const int* __restrict__ neigh32)
{
    if (threadIdx.x == 0 && blockIdx.x == 0) {
        int is64 = 1;
        for (int i = 0; i < 4096; ++i) {
            if (neigh32[2 * i + 1] != 0) { is64 = 0; break; }
        }
        g_is64 = is64;
    }
}

// ---------------------------------------------------------------------------
// Prepack weights for chunk t: per (n, g) item covers k = t*32 + 4g .. +3.
// ---------------------------------------------------------------------------
__global__ __launch_bounds__(256) void prepack_kernel(const float* __restrict__ W)
{
    const int t = blockIdx.x;
    for (int idx = threadIdx.x; idx < COUT * 8; idx += 256) {
        int n = idx >> 3, g = idx & 7;
        int k0 = t * 32 + 4 * g;
        float f0 = W[(k0 + 0) * COUT + n];
        float f1 = W[(k0 + 1) * COUT + n];
        float f2 = W[(k0 + 2) * COUT + n];
        float f3 = W[(k0 + 3) * COUT + n];
        __nv_bfloat162 h01 = __floats2bfloat162_rn(f0, f1);
        __nv_bfloat162 h23 = __floats2bfloat162_rn(f2, f3);
        g_wbf[t * 3072 + n * 16 + 2 * g]     = *reinterpret_cast<unsigned*>(&h01);
        g_wbf[t * 3072 + n * 16 + 2 * g + 1] = *reinterpret_cast<unsigned*>(&h23);
        float2 H01 = __bfloat1622float2(h01);
        float2 H23 = __bfloat1622float2(h23);
        g_w8h[t * 1536 + n * 8 + g] = pack_e4m3(f0, f1, f2, f3);
        g_w8l[t * 1536 + n * 8 + g] = pack_e4m3((f0 - H01.x) * 256.0f,
                                                (f1 - H01.y) * 256.0f,
                                                (f2 - H23.x) * 256.0f,
                                                (f3 - H23.y) * 256.0f);
    }
}

// ---------------------------------------------------------------------------
// Conv kernel: gather-GEMM, bf16 hi·hi on HMMA + fp8 cross terms on QMMA.
// Block = 64 rows x 192 cols, 8 warps as 4(M) x 2(N); warp tile 16x96.
// A gather software-pipelined (LDG for t+1 issued before MMA of t).
// ---------------------------------------------------------------------------
__global__ __launch_bounds__(256) void conv_kernel(
    const float* __restrict__ data,
    const float* __restrict__ bias,
    const void* __restrict__ neigh_raw,
    float* __restrict__ out)
{
    __shared__ __align__(16) unsigned pool[POOLW];
    int*   sSrow = (int*)&pool[O_SROW];
    float* RedS  = (float*)pool;            // overlay after MMA: [4][192]
    float* RedQ  = RedS + 4 * COUT;

    const int tid = threadIdx.x;
    const int lid = tid & 31;
    const int wid = tid >> 5;
    const int wm  = wid >> 1;               // 0..3 (M)
    const int wn  = wid & 1;                // 0..1 (N)
    const int gid = lid >> 2;               // 0..7
    const int tig = lid & 3;                // 0..3
    const int bx  = blockIdx.x;
    const int m0  = bx * BM;

    const int is64 = g_is64;
    const long long* n64 = (const long long*)neigh_raw;
    const int*       n32 = (const int*)neigh_raw;

    // Stage neighbor indices for this row tile.
    for (int idx = tid; idx < BM * KNB; idx += 256) {
        int r  = idx >> 3;
        int kk = idx & 7;
        int m  = m0 + r;
        int srow = -1;
        if (m < M_OUT) {
            long long v = is64 ? n64[(long long)m * KNB + kk]
                               : (long long)n32[(long long)m * KNB + kk];
            if (v >= 0) srow = (int)v;
        }
        sSrow[idx] = srow;
    }
    __syncthreads();

    // Stage items: A = 512 float4 items (2/thread): item -> (row r, group g)
    const int ar0 = tid >> 3,  ag0 = tid & 7;           // item tid
    const int ar1 = (tid + 256) >> 3, ag1 = (tid + 256) & 7;

    // --- prologue: stage chunk 0 ---
    {
        const int kk = 0, c0 = 0;
        float4 f[2] = {make_float4(0,0,0,0), make_float4(0,0,0,0)};
        int s0 = sSrow[ar0 * KNB + kk];
        int s1 = sSrow[ar1 * KNB + kk];
        if (s0 >= 0) f[0] = *(const float4*)(data + s0 * CIN + c0 + 4 * ag0);
        if (s1 >= 0) f[1] = *(const float4*)(data + s1 * CIN + c0 + 4 * ag1);
#pragma unroll
        for (int i = 0; i < 2; ++i) {
            int r = i ? ar1 : ar0, g = i ? ag1 : ag0;
            __nv_bfloat162 h01 = __floats2bfloat162_rn(f[i].x, f[i].y);
            __nv_bfloat162 h23 = __floats2bfloat162_rn(f[i].z, f[i].w);
            pool[O_ABF + r * SBF + 2 * g]     = *reinterpret_cast<unsigned*>(&h01);
            pool[O_ABF + r * SBF + 2 * g + 1] = *reinterpret_cast<unsigned*>(&h23);
            float2 H01 = __bfloat1622float2(h01);
            float2 H23 = __bfloat1622float2(h23);
            pool[O_A8H + r * S8 + g] = pack_e4m3(f[i].x, f[i].y, f[i].z, f[i].w);
            pool[O_A8L + r * S8 + g] = pack_e4m3((f[i].x - H01.x) * 256.0f,
                                                 (f[i].y - H01.y) * 256.0f,
                                                 (f[i].z - H23.x) * 256.0f,
                                                 (f[i].w - H23.y) * 256.0f);
        }
        // B chunk 0
        for (int idx = tid; idx < 768; idx += 256) {      // bf16: [n][wg of 4]
            int n = idx >> 2, wg = idx & 3;
            *(uint4*)&pool[O_BBF + n * SBF + 4 * wg] =
                *(const uint4*)&g_wbf[n * 16 + 4 * wg];
        }
        for (int idx = tid; idx < 384; idx += 256) {      // fp8 hi
            int n = idx >> 1, gg = idx & 1;
            *(uint4*)&pool[O_B8H + n * S8 + 4 * gg] =
                *(const uint4*)&g_w8h[n * 8 + 4 * gg];
        }
        for (int idx = tid; idx < 384; idx += 256) {      // fp8 lo
            int n = idx >> 1, gg = idx & 1;
            *(uint4*)&pool[O_B8L + n * S8 + 4 * gg] =
                *(const uint4*)&g_w8l[n * 8 + 4 * gg];
        }
    }
    __syncthreads();

    float accm[12][4], accc[12][4];
#pragma unroll
    for (int j = 0; j < 12; ++j)
#pragma unroll
        for (int q = 0; q < 4; ++q) { accm[j][q] = 0.0f; accc[j][q] = 0.0f; }

    const int r0 = wm * 16 + gid;

    for (int t = 0; t < NCHUNK; ++t) {
        // ---- issue gather LDGs for chunk t+1 (latency hidden by MMA) ----
        float4 f[2] = {make_float4(0,0,0,0), make_float4(0,0,0,0)};
        if (t + 1 < NCHUNK) {
            const int kk = (t + 1) / 3;
            const int c0 = ((t + 1) % 3) * 32;
            int s0 = sSrow[ar0 * KNB + kk];
            int s1 = sSrow[ar1 * KNB + kk];
            if (s0 >= 0) f[0] = *(const float4*)(data + s0 * CIN + c0 + 4 * ag0);
            if (s1 >= 0) f[1] = *(const float4*)(data + s1 * CIN + c0 + 4 * ag1);
        }

        // ---- load A fragments for chunk t ----
        unsigned ahb[2][4], ah8[4], al8[4];
#pragma unroll
        for (int s = 0; s < 2; ++s) {
            ahb[s][0] = pool[O_ABF + (r0)     * SBF + s * 8 + tig];
            ahb[s][1] = pool[O_ABF + (r0 + 8) * SBF + s * 8 + tig];
            ahb[s][2] = pool[O_ABF + (r0)     * SBF + s * 8 + 4 + tig];
            ahb[s][3] = pool[O_ABF + (r0 + 8) * SBF + s * 8 + 4 + tig];
        }
        ah8[0] = pool[O_A8H + (r0)     * S8 + tig];
        ah8[1] = pool[O_A8H + (r0 + 8) * S8 + tig];
        ah8[2] = pool[O_A8H + (r0)     * S8 + 4 + tig];
        ah8[3] = pool[O_A8H + (r0 + 8) * S8 + 4 + tig];
        al8[0] = pool[O_A8L + (r0)     * S8 + tig];
        al8[1] = pool[O_A8L + (r0 + 8) * S8 + tig];
        al8[2] = pool[O_A8L + (r0)     * S8 + 4 + tig];
        al8[3] = pool[O_A8L + (r0 + 8) * S8 + 4 + tig];

        // ---- MMA burst ----
#pragma unroll
        for (int j = 0; j < 12; ++j) {
            const int n = wn * 96 + j * 8 + gid;
            unsigned b0 = pool[O_BBF + n * SBF + tig];
            unsigned b1 = pool[O_BBF + n * SBF + 4 + tig];
            unsigned b2 = pool[O_BBF + n * SBF + 8 + tig];
            unsigned b3 = pool[O_BBF + n * SBF + 12 + tig];
            HMMA(accm[j], ahb[0][0], ahb[0][1], ahb[0][2], ahb[0][3], b0, b1);
            HMMA(accm[j], ahb[1][0], ahb[1][1], ahb[1][2], ahb[1][3], b2, b3);
            unsigned c0 = pool[O_B8H + n * S8 + tig];
            unsigned c1 = pool[O_B8H + n * S8 + 4 + tig];
            unsigned d0 = pool[O_B8L + n * S8 + tig];
            unsigned d1 = pool[O_B8L + n * S8 + 4 + tig];
            QMMA(accc[j], ah8[0], ah8[1], ah8[2], ah8[3], d0, d1);  // ah·(bl·256)
            QMMA(accc[j], al8[0], al8[1], al8[2], al8[3], c0, c1);  // (al·256)·bh
        }
        __syncthreads();   // all reads of chunk t done

        // ---- store staged chunk t+1 ----
        if (t + 1 < NCHUNK) {
#pragma unroll
            for (int i = 0; i < 2; ++i) {
                int r = i ? ar1 : ar0, g = i ? ag1 : ag0;
                __nv_bfloat162 h01 = __floats2bfloat162_rn(f[i].x, f[i].y);
                __nv_bfloat162 h23 = __floats2bfloat162_rn(f[i].z, f[i].w);
                pool[O_ABF + r * SBF + 2 * g]     = *reinterpret_cast<unsigned*>(&h01);
                pool[O_ABF + r * SBF + 2 * g + 1] = *reinterpret_cast<unsigned*>(&h23);
                float2 H01 = __bfloat1622float2(h01);
                float2 H23 = __bfloat1622float2(h23);
                pool[O_A8H + r * S8 + g] = pack_e4m3(f[i].x, f[i].y, f[i].z, f[i].w);
                pool[O_A8L + r * S8 + g] = pack_e4m3((f[i].x - H01.x) * 256.0f,
                                                     (f[i].y - H01.y) * 256.0f,
                                                     (f[i].z - H23.x) * 256.0f,
                                                     (f[i].w - H23.y) * 256.0f);
            }
            const int tb = t + 1;
            for (int idx = tid; idx < 768; idx += 256) {
                int n = idx >> 2, wg = idx & 3;
                *(uint4*)&pool[O_BBF + n * SBF + 4 * wg] =
                    *(const uint4*)&g_wbf[tb * 3072 + n * 16 + 4 * wg];
            }
            for (int idx = tid; idx < 384; idx += 256) {
                int n = idx >> 1, gg = idx & 1;
                *(uint4*)&pool[O_B8H + n * S8 + 4 * gg] =
                    *(const uint4*)&g_w8h[tb * 1536 + n * 8 + 4 * gg];
            }
            for (int idx = tid; idx < 384; idx += 256) {
                int n = idx >> 1, gg = idx & 1;
                *(uint4*)&pool[O_B8L + n * S8 + 4 * gg] =
                    *(const uint4*)&g_w8l[tb * 1536 + n * 8 + 4 * gg];
            }
        }
        __syncthreads();
    }

    // ---- Epilogue: bias + combined acc + output + BN partials ----
    const int rr0 = m0 + r0;
    const int rr1 = rr0 + 8;
    const bool v0 = (rr0 < M_OUT);
    const bool v1 = (rr1 < M_OUT);

    float cs[24], cq[24];
#pragma unroll
    for (int j = 0; j < 12; ++j) {
        const int cb = wn * 96 + j * 8 + 2 * tig;
        float b0 = __ldg(&bias[cb]);
        float b1 = __ldg(&bias[cb + 1]);
        float v00 = accm[j][0] + accc[j][0] * 0.00390625f + b0;
        float v01 = accm[j][1] + accc[j][1] * 0.00390625f + b1;
        float v10 = accm[j][2] + accc[j][2] * 0.00390625f + b0;
        float v11 = accm[j][3] + accc[j][3] * 0.00390625f + b1;
        if (v0) *(float2*)&out[(long long)rr0 * COUT + cb] = make_float2(v00, v01);
        if (v1) *(float2*)&out[(long long)rr1 * COUT + cb] = make_float2(v10, v11);
        cs[2 * j]     = (v0 ? v00 : 0.0f) + (v1 ? v10 : 0.0f);
        cs[2 * j + 1] = (v0 ? v01 : 0.0f) + (v1 ? v11 : 0.0f);
        cq[2 * j]     = (v0 ? v00 * v00 : 0.0f) + (v1 ? v10 * v10 : 0.0f);
        cq[2 * j + 1] = (v0 ? v01 * v01 : 0.0f) + (v1 ? v11 * v11 : 0.0f);
    }
#pragma unroll
    for (int k = 4; k <= 16; k <<= 1) {
#pragma unroll
        for (int i = 0; i < 24; ++i) {
            cs[i] += __shfl_xor_sync(0xffffffffu, cs[i], k);
            cq[i] += __shfl_xor_sync(0xffffffffu, cq[i], k);
        }
    }
    if (gid == 0) {
#pragma unroll
        for (int j = 0; j < 12; ++j) {
            int col = wn * 96 + j * 8 + 2 * tig;
            RedS[wm * COUT + col]     = cs[2 * j];
            RedS[wm * COUT + col + 1] = cs[2 * j + 1];
            RedQ[wm * COUT + col]     = cq[2 * j];
            RedQ[wm * COUT + col + 1] = cq[2 * j + 1];
        }
    }
    __syncthreads();
    if (tid < COUT) {
        float s = 0.0f, q = 0.0f;
#pragma unroll
        for (int y = 0; y < 4; ++y) {
            s += RedS[y * COUT + tid];
            q += RedQ[y * COUT + tid];
        }
        g_psum[tid * NBLK + bx] = s;
        g_psq[tid * NBLK + bx]  = q;
    }
}

// ---------------------------------------------------------------------------
__global__ __launch_bounds__(256) void stats_kernel(
    const float* __restrict__ gamma,
    const float* __restrict__ beta)
{
    const int c = blockIdx.x;
    const int t = threadIdx.x;
    float s = 0.0f, q = 0.0f;
    for (int b = t; b < NBLK; b += 256) {
        s += g_psum[c * NBLK + b];
        q += g_psq[c * NBLK + b];
    }
    __shared__ float ss[256], sq[256];
    ss[t] = s; sq[t] = q;
    __syncthreads();
    for (int o = 128; o > 0; o >>= 1) {
        if (t < o) { ss[t] += ss[t + o]; sq[t] += sq[t + o]; }
        __syncthreads();
    }
    if (t == 0) {
        float mean = ss[0] / (float)M_OUT;
        float var  = sq[0] / (float)M_OUT - mean * mean;
        float rs   = rsqrtf(var + BN_EPS);
        float sc   = gamma[c] * rs;
        g_scale[c] = sc;
        g_shift[c] = beta[c] - mean * sc;
    }
}

#define NVEC (M_OUT * COUT / 4)
__global__ __launch_bounds__(256) void norm_kernel(float4* __restrict__ out4)
{
    int i = blockIdx.x * 256 + threadIdx.x;
    if (i < NVEC) {
        int c = (i % 48) * 4;
        float4 v = out4[i];
        v.x = v.x * g_scale[c + 0] + g_shift[c + 0];
        v.y = v.y * g_scale[c + 1] + g_shift[c + 1];
        v.z = v.z * g_scale[c + 2] + g_shift[c + 2];
        v.w = v.w * g_scale[c + 3] + g_shift[c + 3];
        out4[i] = v;
    }
}

extern "C" void kernel_launch(void* const* d_in, const int* in_sizes, int n_in,
                              void* d_out, int out_size)
{
    const float* data    = (const float*)d_in[0];
    const float* weights = (const float*)d_in[1];
    const float* bias    = (const float*)d_in[2];
    const float* gamma   = (const float*)d_in[3];
    const float* beta    = (const float*)d_in[4];
    const void*  neigh   = (const void*)d_in[5];
    float* out = (float*)d_out;

    detect_kernel<<<1, 32>>>((const int*)neigh);
    noop_kernel<<<1, 32>>>();                 // pad so conv is the 6th launch
    noop_kernel<<<1, 32>>>();                 // (ncu -s 5 -c 1 captures it)
    noop_kernel<<<1, 32>>>();
    prepack_kernel<<<NCHUNK, 256>>>(weights);
    conv_kernel<<<NBLK, 256>>>(data, bias, neigh, out);
    stats_kernel<<<COUT, 256>>>(gamma, beta);
    norm_kernel<<<(NVEC + 255) / 256, 256>>>((float4*)out);
}

// round 6
// speedup vs baseline: 2.9025x; 2.9025x over previous
#include <cuda_runtime.h>
#include <cuda_fp16.h>

// Problem constants
#define M_OUT   125000
#define KNB     8
#define CIN     96
#define COUT    192
#define BM      128
#define NCHUNK  12                        // K chunks of 64 (768 total)
#define NBLK    977                       // ceil(125000/128)
#define BN_EPS  1e-5f
#define SA      36                        // smem row stride in words (conflict-free)

// Dynamic smem word offsets
#define NW_A    (BM * SA)                 // 4608
#define NW_B    (COUT * SA)               // 6912
#define O_A(s,p)  (((s) * 2 + (p)) * NW_A)        // 0 .. 18432
#define O_B(s)    (18432 + (s) * NW_B)            // .. 32256
#define O_SROW    32256                           // 1024 words
#define POOLW     33280
#define POOLB     (POOLW * 4)                     // 133120 B

// Deterministic scratch
__device__ float g_psum[COUT * NBLK];
__device__ float g_psq [COUT * NBLK];
__device__ float g_scale[COUT];
__device__ float g_shift[COUT];
__device__ int   g_is64;
// Pre-packed fp16 weights: [t][n][w] word = half2 over (k,k+1), k = 64t + 2w
__device__ __align__(16) unsigned g_wf[NCHUNK * COUT * 32];

#define HMMA(d, a0, a1, a2, a3, b0, b1)                                        \
    asm volatile(                                                              \
        "mma.sync.aligned.m16n8k16.row.col.f32.f16.f16.f32 "                   \
        "{%0,%1,%2,%3}, {%4,%5,%6,%7}, {%8,%9}, {%0,%1,%2,%3};"                \
        : "+f"((d)[0]), "+f"((d)[1]), "+f"((d)[2]), "+f"((d)[3])               \
        : "r"(a0), "r"(a1), "r"(a2), "r"(a3), "r"(b0), "r"(b1))

// ---------------------------------------------------------------------------
__global__ void noop_kernel() {}

__global__ void detect_kernel(const int* __restrict__ neigh32)
{
    if (threadIdx.x == 0 && blockIdx.x == 0) {
        int is64 = 1;
        for (int i = 0; i < 4096; ++i) {
            if (neigh32[2 * i + 1] != 0) { is64 = 0; break; }
        }
        g_is64 = is64;
    }
}

// ---------------------------------------------------------------------------
// Prepack weights: fp32 [768][192] -> fp16 pairs [t][n][32 words].
// ---------------------------------------------------------------------------
__global__ __launch_bounds__(256) void prepack_kernel(const float* __restrict__ W)
{
    const int t = blockIdx.x;
    for (int idx = threadIdx.x; idx < COUT * 32; idx += 256) {
        int n = idx >> 5, w = idx & 31;
        int k0 = t * 64 + 2 * w;
        __half2 h = __floats2half2_rn(W[k0 * COUT + n], W[(k0 + 1) * COUT + n]);
        g_wf[t * 6144 + n * 32 + w] = *reinterpret_cast<unsigned*>(&h);
    }
}

// ---------------------------------------------------------------------------
// Conv kernel: gather-GEMM on fp16 tensor cores, A split hi/lo, B single.
// Block = 128 rows x 192 cols, 16 warps as 8(M) x 2(N); warp tile 16x96.
// Double-buffered smem, one sync per chunk, gather pipelined via registers.
// ---------------------------------------------------------------------------
__global__ __launch_bounds__(512) void conv_kernel(
    const float* __restrict__ data,
    const float* __restrict__ bias,
    const void* __restrict__ neigh_raw,
    float* __restrict__ out)
{
    extern __shared__ __align__(16) unsigned pool[];
    int*   sSrow = (int*)&pool[O_SROW];
    float* RedS  = (float*)pool;              // overlay after MMA: [8][192]
    float* RedQ  = RedS + 8 * COUT;

    const int tid = threadIdx.x;
    const int lid = tid & 31;
    const int wid = tid >> 5;                 // 0..15
    const int wm  = wid >> 1;                 // 0..7 (M)
    const int wn  = wid & 1;                  // 0..1 (N)
    const int gid = lid >> 2;                 // 0..7
    const int tig = lid & 3;                  // 0..3
    const int bx  = blockIdx.x;
    const int m0  = bx * BM;

    const int is64 = g_is64;
    const long long* n64 = (const long long*)neigh_raw;
    const int*       n32 = (const int*)neigh_raw;

    // Stage neighbor indices [128][8]
    for (int idx = tid; idx < BM * KNB; idx += 512) {
        int r  = idx >> 3;
        int kk = idx & 7;
        int m  = m0 + r;
        int srow = -1;
        if (m < M_OUT) {
            long long v = is64 ? n64[(long long)m * KNB + kk]
                               : (long long)n32[(long long)m * KNB + kk];
            if (v >= 0) srow = (int)v;
        }
        sSrow[idx] = srow;
    }
    __syncthreads();

    // Gather staging: 2048 float4 items -> 4 per thread. item -> (row, g)
    float4 fst[4];

#define GATHER(T)                                                              \
    _Pragma("unroll")                                                          \
    for (int i = 0; i < 4; ++i) {                                              \
        int idx = tid + 512 * i;                                               \
        int r = idx >> 4, g = idx & 15;                                        \
        int k0 = ((T) << 6) + (g << 2);                                        \
        int kk = k0 / 96, c = k0 - 96 * kk;                                    \
        int srow = sSrow[r * KNB + kk];                                        \
        fst[i] = make_float4(0.f, 0.f, 0.f, 0.f);                              \
        if (srow >= 0) fst[i] = *(const float4*)(data + srow * CIN + c);       \
    }

#define STS_A(S)                                                               \
    _Pragma("unroll")                                                          \
    for (int i = 0; i < 4; ++i) {                                              \
        int idx = tid + 512 * i;                                               \
        int r = idx >> 4, g = idx & 15;                                        \
        __half2 h01 = __floats2half2_rn(fst[i].x, fst[i].y);                   \
        __half2 h23 = __floats2half2_rn(fst[i].z, fst[i].w);                   \
        float2 H01 = __half22float2(h01);                                      \
        float2 H23 = __half22float2(h23);                                      \
        __half2 l01 = __floats2half2_rn(fst[i].x - H01.x, fst[i].y - H01.y);   \
        __half2 l23 = __floats2half2_rn(fst[i].z - H23.x, fst[i].w - H23.y);   \
        *(uint2*)&pool[O_A((S), 0) + r * SA + 2 * g] =                         \
            make_uint2(*reinterpret_cast<unsigned*>(&h01),                     \
                       *reinterpret_cast<unsigned*>(&h23));                    \
        *(uint2*)&pool[O_A((S), 1) + r * SA + 2 * g] =                         \
            make_uint2(*reinterpret_cast<unsigned*>(&l01),                     \
                       *reinterpret_cast<unsigned*>(&l23));                    \
    }

#define COPY_B(T, S)                                                           \
    _Pragma("unroll")                                                          \
    for (int i = 0; i < 3; ++i) {                                              \
        int idx = tid + 512 * i;                                               \
        int n = idx >> 3, wg = idx & 7;                                        \
        *(uint4*)&pool[O_B(S) + n * SA + 4 * wg] =                             \
            *(const uint4*)&g_wf[(T) * 6144 + n * 32 + 4 * wg];                \
    }

    // Prologue: stage chunk 0
    GATHER(0);
    COPY_B(0, 0);
    STS_A(0);
    __syncthreads();

    float acc[12][4];
#pragma unroll
    for (int j = 0; j < 12; ++j)
#pragma unroll
        for (int q = 0; q < 4; ++q) acc[j][q] = 0.0f;

    const int r0 = wm * 16 + gid;

    for (int t = 0; t < NCHUNK; ++t) {
        const int s = t & 1;
        if (t + 1 < NCHUNK) {
            GATHER(t + 1);            // LDGs in flight during MMA burst
            COPY_B(t + 1, s ^ 1);     // L2-resident copy into other buffer
        }

        // MMA burst over 4 k16 steps of this K64 chunk
#pragma unroll
        for (int s2 = 0; s2 < 4; ++s2) {
            const int base = s2 * 8;
            unsigned ah0 = pool[O_A(s, 0) + (r0)     * SA + base + tig];
            unsigned ah1 = pool[O_A(s, 0) + (r0 + 8) * SA + base + tig];
            unsigned ah2 = pool[O_A(s, 0) + (r0)     * SA + base + 4 + tig];
            unsigned ah3 = pool[O_A(s, 0) + (r0 + 8) * SA + base + 4 + tig];
            unsigned al0 = pool[O_A(s, 1) + (r0)     * SA + base + tig];
            unsigned al1 = pool[O_A(s, 1) + (r0 + 8) * SA + base + tig];
            unsigned al2 = pool[O_A(s, 1) + (r0)     * SA + base + 4 + tig];
            unsigned al3 = pool[O_A(s, 1) + (r0 + 8) * SA + base + 4 + tig];
#pragma unroll
            for (int j = 0; j < 12; ++j) {
                const int n = wn * 96 + j * 8 + gid;
                unsigned b0 = pool[O_B(s) + n * SA + base + tig];
                unsigned b1 = pool[O_B(s) + n * SA + base + 4 + tig];
                HMMA(acc[j], ah0, ah1, ah2, ah3, b0, b1);
                HMMA(acc[j], al0, al1, al2, al3, b0, b1);
            }
        }

        if (t + 1 < NCHUNK) STS_A(s ^ 1);
        __syncthreads();
    }

    // ---- Epilogue: bias + output + BN partials ----
    const int rr0 = m0 + r0;
    const int rr1 = rr0 + 8;
    const bool v0 = (rr0 < M_OUT);
    const bool v1 = (rr1 < M_OUT);

    float cs[24], cq[24];
#pragma unroll
    for (int j = 0; j < 12; ++j) {
        const int cb = wn * 96 + j * 8 + 2 * tig;
        float b0 = __ldg(&bias[cb]);
        float b1 = __ldg(&bias[cb + 1]);
        float v00 = acc[j][0] + b0, v01 = acc[j][1] + b1;
        float v10 = acc[j][2] + b0, v11 = acc[j][3] + b1;
        if (v0) *(float2*)&out[(long long)rr0 * COUT + cb] = make_float2(v00, v01);
        if (v1) *(float2*)&out[(long long)rr1 * COUT + cb] = make_float2(v10, v11);
        cs[2 * j]     = (v0 ? v00 : 0.0f) + (v1 ? v10 : 0.0f);
        cs[2 * j + 1] = (v0 ? v01 : 0.0f) + (v1 ? v11 : 0.0f);
        cq[2 * j]     = (v0 ? v00 * v00 : 0.0f) + (v1 ? v10 * v10 : 0.0f);
        cq[2 * j + 1] = (v0 ? v01 * v01 : 0.0f) + (v1 ? v11 * v11 : 0.0f);
    }
#pragma unroll
    for (int k = 4; k <= 16; k <<= 1) {
#pragma unroll
        for (int i = 0; i < 24; ++i) {
            cs[i] += __shfl_xor_sync(0xffffffffu, cs[i], k);
            cq[i] += __shfl_xor_sync(0xffffffffu, cq[i], k);
        }
    }
    if (gid == 0) {
#pragma unroll
        for (int j = 0; j < 12; ++j) {
            int col = wn * 96 + j * 8 + 2 * tig;
            RedS[wm * COUT + col]     = cs[2 * j];
            RedS[wm * COUT + col + 1] = cs[2 * j + 1];
            RedQ[wm * COUT + col]     = cq[2 * j];
            RedQ[wm * COUT + col + 1] = cq[2 * j + 1];
        }
    }
    __syncthreads();
    if (tid < COUT) {
        float s = 0.0f, q = 0.0f;
#pragma unroll
        for (int y = 0; y < 8; ++y) {
            s += RedS[y * COUT + tid];
            q += RedQ[y * COUT + tid];
        }
        g_psum[tid * NBLK + bx] = s;
        g_psq[tid * NBLK + bx]  = q;
    }
}

// ---------------------------------------------------------------------------
__global__ __launch_bounds__(256) void stats_kernel(
    const float* __restrict__ gamma,
    const float* __restrict__ beta)
{
    const int c = blockIdx.x;
    const int t = threadIdx.x;
    float s = 0.0f, q = 0.0f;
    for (int b = t; b < NBLK; b += 256) {
        s += g_psum[c * NBLK + b];
        q += g_psq[c * NBLK + b];
    }
    __shared__ float ss[256], sq[256];
    ss[t] = s; sq[t] = q;
    __syncthreads();
    for (int o = 128; o > 0; o >>= 1) {
        if (t < o) { ss[t] += ss[t + o]; sq[t] += sq[t + o]; }
        __syncthreads();
    }
    if (t == 0) {
        float mean = ss[0] / (float)M_OUT;
        float var  = sq[0] / (float)M_OUT - mean * mean;
        float rs   = rsqrtf(var + BN_EPS);
        float sc   = gamma[c] * rs;
        g_scale[c] = sc;
        g_shift[c] = beta[c] - mean * sc;
    }
}

#define NVEC (M_OUT * COUT / 4)
__global__ __launch_bounds__(256) void norm_kernel(float4* __restrict__ out4)
{
    int i = blockIdx.x * 256 + threadIdx.x;
    if (i < NVEC) {
        int c = (i % 48) * 4;
        float4 v = out4[i];
        v.x = v.x * g_scale[c + 0] + g_shift[c + 0];
        v.y = v.y * g_scale[c + 1] + g_shift[c + 1];
        v.z = v.z * g_scale[c + 2] + g_shift[c + 2];
        v.w = v.w * g_scale[c + 3] + g_shift[c + 3];
        out4[i] = v;
    }
}

extern "C" void kernel_launch(void* const* d_in, const int* in_sizes, int n_in,
                              void* d_out, int out_size)
{
    const float* data    = (const float*)d_in[0];
    const float* weights = (const float*)d_in[1];
    const float* bias    = (const float*)d_in[2];
    const float* gamma   = (const float*)d_in[3];
    const float* beta    = (const float*)d_in[4];
    const void*  neigh   = (const void*)d_in[5];
    float* out = (float*)d_out;

    cudaFuncSetAttribute(conv_kernel, cudaFuncAttributeMaxDynamicSharedMemorySize,
                         POOLB);

    detect_kernel<<<1, 32>>>((const int*)neigh);
    noop_kernel<<<1, 32>>>();                 // pad so conv is the 6th launch
    noop_kernel<<<1, 32>>>();                 // (ncu -s 5 -c 1 captures it)
    noop_kernel<<<1, 32>>>();
    prepack_kernel<<<NCHUNK, 256>>>(weights);
    conv_kernel<<<NBLK, 512, POOLB>>>(data, bias, neigh, out);
    stats_kernel<<<COUT, 256>>>(gamma, beta);
    norm_kernel<<<(NVEC + 255) / 256, 256>>>((float4*)out);
}

// round 9
// speedup vs baseline: 3.8129x; 1.3137x over previous
#include <cuda_runtime.h>
#include <cuda_fp16.h>

// Problem constants
#define M_OUT   125000
#define KNB     8
#define CIN     96
#define COUT    192
#define BM      128
#define NCHUNK  12                        // K chunks of 64 (768 total)
#define NBLK    977                       // ceil(125000/128)
#define BN_EPS  1e-5f
#define SA      36                        // smem row stride in words (conflict-free)

// Dynamic smem word offsets: A hi double-buffered, B double-buffered.
#define NW_A    (BM * SA)                 // 4608
#define NW_B    (COUT * SA)               // 6912
#define O_A(s)    ((s) * NW_A)                    // 0 .. 9216
#define O_B(s)    (9216 + (s) * NW_B)             // .. 23040
#define O_SROW    23040                           // 1024 words
#define POOLW     24064
#define POOLB     (POOLW * 4)                     // 96256 B

// Deterministic scratch
__device__ float g_psum[COUT * NBLK];
__device__ float g_psq [COUT * NBLK];
__device__ float g_scale[COUT];
__device__ float g_shift[COUT];
__device__ int   g_is64;
// Pre-packed fp16 weights: [t][n][w] word = half2 over (k,k+1), k = 64t + 2w
__device__ __align__(16) unsigned g_wf[NCHUNK * COUT * 32];

#define HMMA(d, a0, a1, a2, a3, b0, b1)                                        \
    asm volatile(                                                              \
        "mma.sync.aligned.m16n8k16.row.col.f32.f16.f16.f32 "                   \
        "{%0,%1,%2,%3}, {%4,%5,%6,%7}, {%8,%9}, {%0,%1,%2,%3};"                \
        : "+f"((d)[0]), "+f"((d)[1]), "+f"((d)[2]), "+f"((d)[3])               \
        : "r"(a0), "r"(a1), "r"(a2), "r"(a3), "r"(b0), "r"(b1))

// ---------------------------------------------------------------------------
// Fused prepack (blocks 0..11) + neigh dtype detect (block 12).
// ---------------------------------------------------------------------------
__global__ __launch_bounds__(256) void prep_kernel(const float* __restrict__ W,
                                                   const int* __restrict__ neigh32)
{
    const int t = blockIdx.x;
    if (t < NCHUNK) {
        for (int idx = threadIdx.x; idx < COUT * 32; idx += 256) {
            int n = idx >> 5, w = idx & 31;
            int k0 = t * 64 + 2 * w;
            __half2 h = __floats2half2_rn(W[k0 * COUT + n], W[(k0 + 1) * COUT + n]);
            g_wf[t * 6144 + n * 32 + w] = *reinterpret_cast<unsigned*>(&h);
        }
    } else if (threadIdx.x == 0) {
        // int64 buffer of indices < 2^31 has all odd int32 words zero;
        // int32 buffer of random indices in [0,1e6) certainly does not.
        int is64 = 1;
        for (int i = 0; i < 256; ++i)
            if (neigh32[2 * i + 1] != 0) { is64 = 0; break; }
        g_is64 = is64;
    }
}

// ---------------------------------------------------------------------------
// Conv kernel: gather-GEMM on fp16 tensor cores (A single fp16, B single fp16).
// Block = 128 rows x 192 cols, 16 warps as 8(M) x 2(N); warp tile 16x96.
// Double-buffered smem, one sync per chunk, gather pipelined via registers.
// ---------------------------------------------------------------------------
__global__ __launch_bounds__(512) void conv_kernel(
    const float* __restrict__ data,
    const float* __restrict__ bias,
    const void* __restrict__ neigh_raw,
    float* __restrict__ out)
{
    extern __shared__ __align__(16) unsigned pool[];
    int*   sSrow = (int*)&pool[O_SROW];
    float* RedS  = (float*)pool;              // overlay after MMA: [8][192]
    float* RedQ  = RedS + 8 * COUT;

    const int tid = threadIdx.x;
    const int lid = tid & 31;
    const int wid = tid >> 5;                 // 0..15
    const int wm  = wid >> 1;                 // 0..7 (M)
    const int wn  = wid & 1;                  // 0..1 (N)
    const int gid = lid >> 2;                 // 0..7
    const int tig = lid & 3;                  // 0..3
    const int bx  = blockIdx.x;
    const int m0  = bx * BM;

    const int is64 = g_is64;
    const long long* n64 = (const long long*)neigh_raw;
    const int*       n32 = (const int*)neigh_raw;

    // Stage neighbor indices [128][8]
    for (int idx = tid; idx < BM * KNB; idx += 512) {
        int r  = idx >> 3;
        int kk = idx & 7;
        int m  = m0 + r;
        int srow = -1;
        if (m < M_OUT) {
            long long v = is64 ? n64[(long long)m * KNB + kk]
                               : (long long)n32[(long long)m * KNB + kk];
            if (v >= 0) srow = (int)v;
        }
        sSrow[idx] = srow;
    }
    __syncthreads();

    // Gather staging: 2048 float4 items -> 4 per thread. item -> (row, g)
    float4 fst[4];

#define GATHER(T)                                                              \
    _Pragma("unroll")                                                          \
    for (int i = 0; i < 4; ++i) {                                              \
        int idx = tid + 512 * i;                                               \
        int r = idx >> 4, g = idx & 15;                                        \
        int k0 = ((T) << 6) + (g << 2);                                        \
        int kk = k0 / 96, c = k0 - 96 * kk;                                    \
        int srow = sSrow[r * KNB + kk];                                        \
        fst[i] = make_float4(0.f, 0.f, 0.f, 0.f);                              \
        if (srow >= 0) fst[i] = *(const float4*)(data + srow * CIN + c);       \
    }

#define STS_A(S)                                                               \
    _Pragma("unroll")                                                          \
    for (int i = 0; i < 4; ++i) {                                              \
        int idx = tid + 512 * i;                                               \
        int r = idx >> 4, g = idx & 15;                                        \
        __half2 h01 = __floats2half2_rn(fst[i].x, fst[i].y);                   \
        __half2 h23 = __floats2half2_rn(fst[i].z, fst[i].w);                   \
        *(uint2*)&pool[O_A(S) + r * SA + 2 * g] =                              \
            make_uint2(*reinterpret_cast<unsigned*>(&h01),                     \
                       *reinterpret_cast<unsigned*>(&h23));                    \
    }

#define COPY_B(T, S)                                                           \
    _Pragma("unroll")                                                          \
    for (int i = 0; i < 3; ++i) {                                              \
        int idx = tid + 512 * i;                                               \
        int n = idx >> 3, wg = idx & 7;                                        \
        *(uint4*)&pool[O_B(S) + n * SA + 4 * wg] =                             \
            *(const uint4*)&g_wf[(T) * 6144 + n * 32 + 4 * wg];                \
    }

    // Prologue: stage chunk 0
    GATHER(0);
    COPY_B(0, 0);
    STS_A(0);
    __syncthreads();

    float acc[12][4];
#pragma unroll
    for (int j = 0; j < 12; ++j)
#pragma unroll
        for (int q = 0; q < 4; ++q) acc[j][q] = 0.0f;

    const int r0 = wm * 16 + gid;

    for (int t = 0; t < NCHUNK; ++t) {
        const int s = t & 1;
        if (t + 1 < NCHUNK) {
            GATHER(t + 1);            // LDGs in flight during MMA burst
            COPY_B(t + 1, s ^ 1);     // L2-resident copy into other buffer
        }

        // MMA burst over 4 k16 steps of this K64 chunk
#pragma unroll
        for (int s2 = 0; s2 < 4; ++s2) {
            const int base = s2 * 8;
            unsigned a0 = pool[O_A(s) + (r0)     * SA + base + tig];
            unsigned a1 = pool[O_A(s) + (r0 + 8) * SA + base + tig];
            unsigned a2 = pool[O_A(s) + (r0)     * SA + base + 4 + tig];
            unsigned a3 = pool[O_A(s) + (r0 + 8) * SA + base + 4 + tig];
#pragma unroll
            for (int j = 0; j < 12; ++j) {
                const int n = wn * 96 + j * 8 + gid;
                unsigned b0 = pool[O_B(s) + n * SA + base + tig];
                unsigned b1 = pool[O_B(s) + n * SA + base + 4 + tig];
                HMMA(acc[j], a0, a1, a2, a3, b0, b1);
            }
        }

        if (t + 1 < NCHUNK) STS_A(s ^ 1);
        __syncthreads();
    }

    // ---- Epilogue: bias + output + BN partials ----
    const int rr0 = m0 + r0;
    const int rr1 = rr0 + 8;
    const bool v0 = (rr0 < M_OUT);
    const bool v1 = (rr1 < M_OUT);

    float cs[24], cq[24];
#pragma unroll
    for (int j = 0; j < 12; ++j) {
        const int cb = wn * 96 + j * 8 + 2 * tig;
        float b0 = __ldg(&bias[cb]);
        float b1 = __ldg(&bias[cb + 1]);
        float v00 = acc[j][0] + b0, v01 = acc[j][1] + b1;
        float v10 = acc[j][2] + b0, v11 = acc[j][3] + b1;
        if (v0) *(float2*)&out[(long long)rr0 * COUT + cb] = make_float2(v00, v01);
        if (v1) *(float2*)&out[(long long)rr1 * COUT + cb] = make_float2(v10, v11);
        cs[2 * j]     = (v0 ? v00 : 0.0f) + (v1 ? v10 : 0.0f);
        cs[2 * j + 1] = (v0 ? v01 : 0.0f) + (v1 ? v11 : 0.0f);
        cq[2 * j]     = (v0 ? v00 * v00 : 0.0f) + (v1 ? v10 * v10 : 0.0f);
        cq[2 * j + 1] = (v0 ? v01 * v01 : 0.0f) + (v1 ? v11 * v11 : 0.0f);
    }
#pragma unroll
    for (int k = 4; k <= 16; k <<= 1) {
#pragma unroll
        for (int i = 0; i < 24; ++i) {
            cs[i] += __shfl_xor_sync(0xffffffffu, cs[i], k);
            cq[i] += __shfl_xor_sync(0xffffffffu, cq[i], k);
        }
    }
    if (gid == 0) {
#pragma unroll
        for (int j = 0; j < 12; ++j) {
            int col = wn * 96 + j * 8 + 2 * tig;
            RedS[wm * COUT + col]     = cs[2 * j];
            RedS[wm * COUT + col + 1] = cs[2 * j + 1];
            RedQ[wm * COUT + col]     = cq[2 * j];
            RedQ[wm * COUT + col + 1] = cq[2 * j + 1];
        }
    }
    __syncthreads();
    if (tid < COUT) {
        float s = 0.0f, q = 0.0f;
#pragma unroll
        for (int y = 0; y < 8; ++y) {
            s += RedS[y * COUT + tid];
            q += RedQ[y * COUT + tid];
        }
        g_psum[tid * NBLK + bx] = s;
        g_psq[tid * NBLK + bx]  = q;
    }
}

// ---------------------------------------------------------------------------
__global__ __launch_bounds__(256) void stats_kernel(
    const float* __restrict__ gamma,
    const float* __restrict__ beta)
{
    const int c = blockIdx.x;
    const int t = threadIdx.x;
    float s = 0.0f, q = 0.0f;
    for (int b = t; b < NBLK; b += 256) {
        s += g_psum[c * NBLK + b];
        q += g_psq[c * NBLK + b];
    }
    __shared__ float ss[256], sq[256];
    ss[t] = s; sq[t] = q;
    __syncthreads();
    for (int o = 128; o > 0; o >>= 1) {
        if (t < o) { ss[t] += ss[t + o]; sq[t] += sq[t + o]; }
        __syncthreads();
    }
    if (t == 0) {
        float mean = ss[0] / (float)M_OUT;
        float var  = sq[0] / (float)M_OUT - mean * mean;
        float rs   = rsqrtf(var + BN_EPS);
        float sc   = gamma[c] * rs;
        g_scale[c] = sc;
        g_shift[c] = beta[c] - mean * sc;
    }
}

// ---------------------------------------------------------------------------
// Normalize: in-place affine; scale/shift cached in smem; 2 float4 per thread.
// Each block covers 512 float4 items — grid divisor MUST be 512.
// ---------------------------------------------------------------------------
#define NVEC (M_OUT * COUT / 4)   // 6,000,000
__global__ __launch_bounds__(256) void norm_kernel(float4* __restrict__ out4)
{
    __shared__ float sScale[COUT], sShift[COUT];
    if (threadIdx.x < COUT) {
        sScale[threadIdx.x] = g_scale[threadIdx.x];
        sShift[threadIdx.x] = g_shift[threadIdx.x];
    }
    __syncthreads();

    int i0 = blockIdx.x * 512 + threadIdx.x;
#pragma unroll
    for (int u = 0; u < 2; ++u) {
        int i = i0 + u * 256;
        if (i < NVEC) {
            int c = (i % 48) * 4;
            float4 v = out4[i];
            v.x = v.x * sScale[c + 0] + sShift[c + 0];
            v.y = v.y * sScale[c + 1] + sShift[c + 1];
            v.z = v.z * sScale[c + 2] + sShift[c + 2];
            v.w = v.w * sScale[c + 3] + sShift[c + 3];
            out4[i] = v;
        }
    }
}

extern "C" void kernel_launch(void* const* d_in, const int* in_sizes, int n_in,
                              void* d_out, int out_size)
{
    const float* data    = (const float*)d_in[0];
    const float* weights = (const float*)d_in[1];
    const float* bias    = (const float*)d_in[2];
    const float* gamma   = (const float*)d_in[3];
    const float* beta    = (const float*)d_in[4];
    const void*  neigh   = (const void*)d_in[5];
    float* out = (float*)d_out;

    cudaFuncSetAttribute(conv_kernel, cudaFuncAttributeMaxDynamicSharedMemorySize,
                         POOLB);

    prep_kernel<<<NCHUNK + 1, 256>>>(weights, (const int*)neigh);
    conv_kernel<<<NBLK, 512, POOLB>>>(data, bias, neigh, out);
    stats_kernel<<<COUT, 256>>>(gamma, beta);
    norm_kernel<<<(NVEC + 511) / 512, 256>>>((float4*)out);
}

// round 10
// speedup vs baseline: 4.1320x; 1.0837x over previous
#include <cuda_runtime.h>
#include <cuda_fp16.h>

// Problem constants
#define M_OUT   125000
#define KNB     8
#define CIN     96
#define COUT    192
#define BM      128
#define NCHUNK  12                        // K chunks of 64 (768 total)
#define NBLK    977                       // ceil(125000/128)
#define BN_EPS  1e-5f
#define SA      36                        // smem row stride in words (conflict-free)

// Dynamic smem word offsets: A double-buffered, B double-buffered.
#define NW_A    (BM * SA)                 // 4608
#define NW_B    (COUT * SA)               // 6912
#define O_A(s)    ((s) * NW_A)                    // 0 .. 9216
#define O_B(s)    (9216 + (s) * NW_B)             // .. 23040
#define O_SROW    23040                           // 1024 words
#define POOLW     24064
#define POOLB     (POOLW * 4)                     // 96256 B

// Deterministic scratch
__device__ float g_psum[COUT * NBLK];
__device__ float g_psq [COUT * NBLK];
__device__ float g_scale[COUT];
__device__ float g_shift[COUT];
__device__ int   g_is64;
// Pre-packed fp16 weights: [t][n][w] word = half2 over (k,k+1), k = 64t + 2w
__device__ __align__(16) unsigned g_wf[NCHUNK * COUT * 32];

#define HMMA(d, a0, a1, a2, a3, b0, b1)                                        \
    asm volatile(                                                              \
        "mma.sync.aligned.m16n8k16.row.col.f32.f16.f16.f32 "                   \
        "{%0,%1,%2,%3}, {%4,%5,%6,%7}, {%8,%9}, {%0,%1,%2,%3};"                \
        : "+f"((d)[0]), "+f"((d)[1]), "+f"((d)[2]), "+f"((d)[3])               \
        : "r"(a0), "r"(a1), "r"(a2), "r"(a3), "r"(b0), "r"(b1))

#define LDSM4(r0, r1, r2, r3, addr)                                            \
    asm volatile("ldmatrix.sync.aligned.m8n8.x4.shared.b16 {%0,%1,%2,%3}, [%4];" \
        : "=r"(r0), "=r"(r1), "=r"(r2), "=r"(r3) : "r"(addr))

// ---------------------------------------------------------------------------
// Fused prepack (blocks 0..11) + neigh dtype detect (block 12).
// ---------------------------------------------------------------------------
__global__ __launch_bounds__(256) void prep_kernel(const float* __restrict__ W,
                                                   const int* __restrict__ neigh32)
{
    const int t = blockIdx.x;
    if (t < NCHUNK) {
        for (int idx = threadIdx.x; idx < COUT * 32; idx += 256) {
            int n = idx >> 5, w = idx & 31;
            int k0 = t * 64 + 2 * w;
            __half2 h = __floats2half2_rn(W[k0 * COUT + n], W[(k0 + 1) * COUT + n]);
            g_wf[t * 6144 + n * 32 + w] = *reinterpret_cast<unsigned*>(&h);
        }
    } else if (threadIdx.x == 0) {
        int is64 = 1;
        for (int i = 0; i < 256; ++i)
            if (neigh32[2 * i + 1] != 0) { is64 = 0; break; }
        g_is64 = is64;
    }
}

// ---------------------------------------------------------------------------
// Conv kernel: gather-GEMM on fp16 tensor cores.
// Block = 128 rows x 192 cols, 16 warps as 4(M) x 4(N); warp tile 32x48
// (minimizes smem crossbar traffic). Fragments via ldmatrix.x4.
// ---------------------------------------------------------------------------
__global__ __launch_bounds__(512) void conv_kernel(
    const float* __restrict__ data,
    const float* __restrict__ bias,
    const void* __restrict__ neigh_raw,
    float* __restrict__ out)
{
    extern __shared__ __align__(16) unsigned pool[];
    int*   sSrow = (int*)&pool[O_SROW];
    float* RedS  = (float*)pool;              // overlay after MMA: [4][192]
    float* RedQ  = RedS + 4 * COUT;

    const int tid = threadIdx.x;
    const int lid = tid & 31;
    const int wid = tid >> 5;                 // 0..15
    const int wm  = wid & 3;                  // 0..3 (M): rows wm*32..+31
    const int wn  = wid >> 2;                 // 0..3 (N): cols wn*48..+47
    const int gid = lid >> 2;                 // 0..7
    const int tig = lid & 3;                  // 0..3
    const int bx  = blockIdx.x;
    const int m0  = bx * BM;

    const int is64 = g_is64;
    const long long* n64 = (const long long*)neigh_raw;
    const int*       n32 = (const int*)neigh_raw;

    // Stage neighbor indices [128][8]
    for (int idx = tid; idx < BM * KNB; idx += 512) {
        int r  = idx >> 3;
        int kk = idx & 7;
        int m  = m0 + r;
        int srow = -1;
        if (m < M_OUT) {
            long long v = is64 ? n64[(long long)m * KNB + kk]
                               : (long long)n32[(long long)m * KNB + kk];
            if (v >= 0) srow = (int)v;
        }
        sSrow[idx] = srow;
    }
    __syncthreads();

    // ldmatrix lane-static addresses (byte offsets into pool)
    const unsigned sbase = (unsigned)__cvta_generic_to_shared(pool);
    // A x4 tile: rows r0..r0+15 (lane&15), word +4 for k8..15 (lane&16)
    const unsigned aLane = sbase +
        (((wm * 32 + (lid & 15)) * SA + ((lid & 16) ? 4u : 0u)) << 2);
    // B x4 tile: j-pair selected by lane&16, word +4 by lane&8
    const unsigned bLane = sbase + ((O_B(0) +
        ((wn * 48 + ((lid >> 4) & 1) * 8 + (lid & 7)) * SA +
         ((lid & 8) ? 4u : 0u))) << 2);

    // Gather staging: 2048 float4 items -> 4 per thread. item -> (row, g)
    float4 fst[4];

#define GATHER(T)                                                              \
    _Pragma("unroll")                                                          \
    for (int i = 0; i < 4; ++i) {                                              \
        int idx = tid + 512 * i;                                               \
        int r = idx >> 4, g = idx & 15;                                        \
        int k0 = ((T) << 6) + (g << 2);                                        \
        int kk = k0 / 96, c = k0 - 96 * kk;                                    \
        int srow = sSrow[r * KNB + kk];                                        \
        fst[i] = make_float4(0.f, 0.f, 0.f, 0.f);                              \
        if (srow >= 0) fst[i] = *(const float4*)(data + srow * CIN + c);       \
    }

#define STS_A(S)                                                               \
    _Pragma("unroll")                                                          \
    for (int i = 0; i < 4; ++i) {                                              \
        int idx = tid + 512 * i;                                               \
        int r = idx >> 4, g = idx & 15;                                        \
        __half2 h01 = __floats2half2_rn(fst[i].x, fst[i].y);                   \
        __half2 h23 = __floats2half2_rn(fst[i].z, fst[i].w);                   \
        *(uint2*)&pool[O_A(S) + r * SA + 2 * g] =                              \
            make_uint2(*reinterpret_cast<unsigned*>(&h01),                     \
                       *reinterpret_cast<unsigned*>(&h23));                    \
    }

#define COPY_B(T, S)                                                           \
    _Pragma("unroll")                                                          \
    for (int i = 0; i < 3; ++i) {                                              \
        int idx = tid + 512 * i;                                               \
        int n = idx >> 3, wg = idx & 7;                                        \
        *(uint4*)&pool[O_B(S) + n * SA + 4 * wg] =                             \
            *(const uint4*)&g_wf[(T) * 6144 + n * 32 + 4 * wg];                \
    }

    // Prologue: stage chunk 0
    GATHER(0);
    COPY_B(0, 0);
    STS_A(0);
    __syncthreads();

    float acc[2][6][4];
#pragma unroll
    for (int p = 0; p < 2; ++p)
#pragma unroll
        for (int j = 0; j < 6; ++j)
#pragma unroll
            for (int q = 0; q < 4; ++q) acc[p][j][q] = 0.0f;

    for (int t = 0; t < NCHUNK; ++t) {
        const int s = t & 1;
        if (t + 1 < NCHUNK) {
            GATHER(t + 1);            // LDGs in flight during MMA burst
            COPY_B(t + 1, s ^ 1);     // L2-resident copy into other buffer
        }

        const unsigned aS = aLane + (unsigned)(s * NW_A * 4);
        const unsigned bS = bLane + (unsigned)(s * NW_B * 4);

        // MMA burst over 4 k16 steps of this K64 chunk
#pragma unroll
        for (int s2 = 0; s2 < 4; ++s2) {
            const unsigned ko = (unsigned)(32 * s2);   // 8 words per k16 step
            unsigned ap0[4], ap1[4], bb[12];
            LDSM4(ap0[0], ap0[1], ap0[2], ap0[3], aS + ko);
            LDSM4(ap1[0], ap1[1], ap1[2], ap1[3], aS + (unsigned)(16 * SA * 4) + ko);
            LDSM4(bb[0], bb[1], bb[2],  bb[3],  bS + ko);
            LDSM4(bb[4], bb[5], bb[6],  bb[7],  bS + (unsigned)(16 * SA * 4) + ko);
            LDSM4(bb[8], bb[9], bb[10], bb[11], bS + (unsigned)(32 * SA * 4) + ko);
#pragma unroll
            for (int j = 0; j < 6; ++j) {
                HMMA(acc[0][j], ap0[0], ap0[1], ap0[2], ap0[3], bb[2*j], bb[2*j+1]);
                HMMA(acc[1][j], ap1[0], ap1[1], ap1[2], ap1[3], bb[2*j], bb[2*j+1]);
            }
        }

        if (t + 1 < NCHUNK) STS_A(s ^ 1);
        __syncthreads();
    }

    // ---- Epilogue: bias + output + BN partials ----
    float cs[12], cq[12];
#pragma unroll
    for (int i = 0; i < 12; ++i) { cs[i] = 0.0f; cq[i] = 0.0f; }

#pragma unroll
    for (int j = 0; j < 6; ++j) {
        const int cb = wn * 48 + j * 8 + 2 * tig;
        float b0 = __ldg(&bias[cb]);
        float b1 = __ldg(&bias[cb + 1]);
#pragma unroll
        for (int p = 0; p < 2; ++p) {
            const int rb = m0 + wm * 32 + p * 16 + gid;
            const bool v0 = (rb < M_OUT);
            const bool v1 = (rb + 8 < M_OUT);
            float v00 = acc[p][j][0] + b0, v01 = acc[p][j][1] + b1;
            float v10 = acc[p][j][2] + b0, v11 = acc[p][j][3] + b1;
            if (v0) *(float2*)&out[(long long)rb * COUT + cb] = make_float2(v00, v01);
            if (v1) *(float2*)&out[(long long)(rb + 8) * COUT + cb] = make_float2(v10, v11);
            cs[2*j]   += (v0 ? v00 : 0.0f) + (v1 ? v10 : 0.0f);
            cs[2*j+1] += (v0 ? v01 : 0.0f) + (v1 ? v11 : 0.0f);
            cq[2*j]   += (v0 ? v00 * v00 : 0.0f) + (v1 ? v10 * v10 : 0.0f);
            cq[2*j+1] += (v0 ? v01 * v01 : 0.0f) + (v1 ? v11 * v11 : 0.0f);
        }
    }
    // reduce across gid (lane bits 2,3,4)
#pragma unroll
    for (int k = 4; k <= 16; k <<= 1) {
#pragma unroll
        for (int i = 0; i < 12; ++i) {
            cs[i] += __shfl_xor_sync(0xffffffffu, cs[i], k);
            cq[i] += __shfl_xor_sync(0xffffffffu, cq[i], k);
        }
    }
    if (gid == 0) {
#pragma unroll
        for (int j = 0; j < 6; ++j) {
            int col = wn * 48 + j * 8 + 2 * tig;
            RedS[wm * COUT + col]     = cs[2*j];
            RedS[wm * COUT + col + 1] = cs[2*j+1];
            RedQ[wm * COUT + col]     = cq[2*j];
            RedQ[wm * COUT + col + 1] = cq[2*j+1];
        }
    }
    __syncthreads();
    if (tid < COUT) {
        float s = 0.0f, q = 0.0f;
#pragma unroll
        for (int y = 0; y < 4; ++y) {
            s += RedS[y * COUT + tid];
            q += RedQ[y * COUT + tid];
        }
        g_psum[tid * NBLK + bx] = s;
        g_psq[tid * NBLK + bx]  = q;
    }
}

// ---------------------------------------------------------------------------
__global__ __launch_bounds__(256) void stats_kernel(
    const float* __restrict__ gamma,
    const float* __restrict__ beta)
{
    const int c = blockIdx.x;
    const int t = threadIdx.x;
    float s = 0.0f, q = 0.0f;
    for (int b = t; b < NBLK; b += 256) {
        s += g_psum[c * NBLK + b];
        q += g_psq[c * NBLK + b];
    }
    __shared__ float ss[256], sq[256];
    ss[t] = s; sq[t] = q;
    __syncthreads();
    for (int o = 128; o > 0; o >>= 1) {
        if (t < o) { ss[t] += ss[t + o]; sq[t] += sq[t + o]; }
        __syncthreads();
    }
    if (t == 0) {
        float mean = ss[0] / (float)M_OUT;
        float var  = sq[0] / (float)M_OUT - mean * mean;
        float rs   = rsqrtf(var + BN_EPS);
        float sc   = gamma[c] * rs;
        g_scale[c] = sc;
        g_shift[c] = beta[c] - mean * sc;
    }
}

// ---------------------------------------------------------------------------
// Normalize: in-place affine; scale/shift cached in smem; 2 float4 per thread.
// Each block covers 512 float4 items — grid divisor MUST be 512.
// ---------------------------------------------------------------------------
#define NVEC (M_OUT * COUT / 4)   // 6,000,000
__global__ __launch_bounds__(256) void norm_kernel(float4* __restrict__ out4)
{
    __shared__ float sScale[COUT], sShift[COUT];
    if (threadIdx.x < COUT) {
        sScale[threadIdx.x] = g_scale[threadIdx.x];
        sShift[threadIdx.x] = g_shift[threadIdx.x];
    }
    __syncthreads();

    int i0 = blockIdx.x * 512 + threadIdx.x;
#pragma unroll
    for (int u = 0; u < 2; ++u) {
        int i = i0 + u * 256;
        if (i < NVEC) {
            int c = (i % 48) * 4;
            float4 v = out4[i];
            v.x = v.x * sScale[c + 0] + sShift[c + 0];
            v.y = v.y * sScale[c + 1] + sShift[c + 1];
            v.z = v.z * sScale[c + 2] + sShift[c + 2];
            v.w = v.w * sScale[c + 3] + sShift[c + 3];
            out4[i] = v;
        }
    }
}

extern "C" void kernel_launch(void* const* d_in, const int* in_sizes, int n_in,
                              void* d_out, int out_size)
{
    const float* data    = (const float*)d_in[0];
    const float* weights = (const float*)d_in[1];
    const float* bias    = (const float*)d_in[2];
    const float* gamma   = (const float*)d_in[3];
    const float* beta    = (const float*)d_in[4];
    const void*  neigh   = (const void*)d_in[5];
    float* out = (float*)d_out;

    cudaFuncSetAttribute(conv_kernel, cudaFuncAttributeMaxDynamicSharedMemorySize,
                         POOLB);

    prep_kernel<<<NCHUNK + 1, 256>>>(weights, (const int*)neigh);
    conv_kernel<<<NBLK, 512, POOLB>>>(data, bias, neigh, out);
    stats_kernel<<<COUT, 256>>>(gamma, beta);
    norm_kernel<<<(NVEC + 511) / 512, 256>>>((float4*)out);
}

// round 11
// speedup vs baseline: 4.5539x; 1.1021x over previous
#include <cuda_runtime.h>
#include <cuda_fp16.h>

// Problem constants
#define M_OUT   125000
#define KNB     8
#define CIN     96
#define COUT    192
#define BM      64
#define NCHUNK  12                        // K chunks of 64 (768 total)
#define NBLK    1954                      // ceil(125000/64)
#define BN_EPS  1e-5f
#define SA      36                        // smem row stride in words (conflict-free)

// Dynamic smem word offsets: A double-buffered, B double-buffered.
#define NW_A    (BM * SA)                 // 2304
#define NW_B    (COUT * SA)               // 6912
#define O_A(s)    ((s) * NW_A)                    // 0 .. 4608
#define O_B(s)    (4608 + (s) * NW_B)             // .. 18432
#define O_SROW    18432                           // 512 words
#define POOLW     18944
#define POOLB     (POOLW * 4)                     // 75776 B -> 2 CTAs/SM

// Deterministic scratch
__device__ float g_psum[COUT * NBLK];
__device__ float g_psq [COUT * NBLK];
__device__ float g_scale[COUT];
__device__ float g_shift[COUT];
__device__ int   g_is64;
// Pre-packed fp16 weights: [t][n][w] word = half2 over (k,k+1), k = 64t + 2w
__device__ __align__(16) unsigned g_wf[NCHUNK * COUT * 32];

#define HMMA(d, a0, a1, a2, a3, b0, b1)                                        \
    asm volatile(                                                              \
        "mma.sync.aligned.m16n8k16.row.col.f32.f16.f16.f32 "                   \
        "{%0,%1,%2,%3}, {%4,%5,%6,%7}, {%8,%9}, {%0,%1,%2,%3};"                \
        : "+f"((d)[0]), "+f"((d)[1]), "+f"((d)[2]), "+f"((d)[3])               \
        : "r"(a0), "r"(a1), "r"(a2), "r"(a3), "r"(b0), "r"(b1))

#define LDSM4(r0, r1, r2, r3, addr)                                            \
    asm volatile("ldmatrix.sync.aligned.m8n8.x4.shared.b16 {%0,%1,%2,%3}, [%4];" \
        : "=r"(r0), "=r"(r1), "=r"(r2), "=r"(r3) : "r"(addr))

// ---------------------------------------------------------------------------
// Fused prepack (blocks 0..11) + neigh dtype detect (block 12).
// ---------------------------------------------------------------------------
__global__ __launch_bounds__(256) void prep_kernel(const float* __restrict__ W,
                                                   const int* __restrict__ neigh32)
{
    const int t = blockIdx.x;
    if (t < NCHUNK) {
        for (int idx = threadIdx.x; idx < COUT * 32; idx += 256) {
            int n = idx >> 5, w = idx & 31;
            int k0 = t * 64 + 2 * w;
            __half2 h = __floats2half2_rn(W[k0 * COUT + n], W[(k0 + 1) * COUT + n]);
            g_wf[t * 6144 + n * 32 + w] = *reinterpret_cast<unsigned*>(&h);
        }
    } else if (threadIdx.x == 0) {
        int is64 = 1;
        for (int i = 0; i < 256; ++i)
            if (neigh32[2 * i + 1] != 0) { is64 = 0; break; }
        g_is64 = is64;
    }
}

// ---------------------------------------------------------------------------
// Conv kernel: gather-GEMM on fp16 tensor cores.
// Block = 64 rows x 192 cols, 8 warps as 2(M) x 4(N); warp tile 32x48.
// 2 CTAs/SM so one CTA's HMMA bursts overlap the other's LDS/sync bubbles.
// ---------------------------------------------------------------------------
__global__ __launch_bounds__(256, 2) void conv_kernel(
    const float* __restrict__ data,
    const float* __restrict__ bias,
    const void* __restrict__ neigh_raw,
    float* __restrict__ out)
{
    extern __shared__ __align__(16) unsigned pool[];
    int*   sSrow = (int*)&pool[O_SROW];
    float* RedS  = (float*)pool;              // overlay after MMA: [2][192]
    float* RedQ  = RedS + 2 * COUT;

    const int tid = threadIdx.x;
    const int lid = tid & 31;
    const int wid = tid >> 5;                 // 0..7
    const int wm  = wid & 1;                  // 0..1 (M): rows wm*32..+31
    const int wn  = wid >> 1;                 // 0..3 (N): cols wn*48..+47
    const int gid = lid >> 2;                 // 0..7
    const int tig = lid & 3;                  // 0..3
    const int bx  = blockIdx.x;
    const int m0  = bx * BM;

    const int is64 = g_is64;
    const long long* n64 = (const long long*)neigh_raw;
    const int*       n32 = (const int*)neigh_raw;

    // Stage neighbor indices [64][8]
    for (int idx = tid; idx < BM * KNB; idx += 256) {
        int r  = idx >> 3;
        int kk = idx & 7;
        int m  = m0 + r;
        int srow = -1;
        if (m < M_OUT) {
            long long v = is64 ? n64[(long long)m * KNB + kk]
                               : (long long)n32[(long long)m * KNB + kk];
            if (v >= 0) srow = (int)v;
        }
        sSrow[idx] = srow;
    }
    __syncthreads();

    // ldmatrix lane-static addresses (byte offsets into pool)
    const unsigned sbase = (unsigned)__cvta_generic_to_shared(pool);
    // A x4 tile: rows r..r+15 (lane&15), word +4 for k8..15 (lane&16)
    const unsigned aLane = sbase +
        (((wm * 32 + (lid & 15)) * SA + ((lid & 16) ? 4u : 0u)) << 2);
    // B x4 tile: j-pair selected by lane&16, word +4 by lane&8
    const unsigned bLane = sbase + ((O_B(0) +
        ((wn * 48 + ((lid >> 4) & 1) * 8 + (lid & 7)) * SA +
         ((lid & 8) ? 4u : 0u))) << 2);

    // Gather staging: 1024 float4 items -> 4 per thread. item -> (row, g)
    float4 fst[4];

#define GATHER(T)                                                              \
    _Pragma("unroll")                                                          \
    for (int i = 0; i < 4; ++i) {                                              \
        int idx = tid + 256 * i;                                               \
        int r = idx >> 4, g = idx & 15;                                        \
        int k0 = ((T) << 6) + (g << 2);                                        \
        int kk = k0 / 96, c = k0 - 96 * kk;                                    \
        int srow = sSrow[r * KNB + kk];                                        \
        fst[i] = make_float4(0.f, 0.f, 0.f, 0.f);                              \
        if (srow >= 0) fst[i] = *(const float4*)(data + srow * CIN + c);       \
    }

#define STS_A(S)                                                               \
    _Pragma("unroll")                                                          \
    for (int i = 0; i < 4; ++i) {                                              \
        int idx = tid + 256 * i;                                               \
        int r = idx >> 4, g = idx & 15;                                        \
        __half2 h01 = __floats2half2_rn(fst[i].x, fst[i].y);                   \
        __half2 h23 = __floats2half2_rn(fst[i].z, fst[i].w);                   \
        *(uint2*)&pool[O_A(S) + r * SA + 2 * g] =                              \
            make_uint2(*reinterpret_cast<unsigned*>(&h01),                     \
                       *reinterpret_cast<unsigned*>(&h23));                    \
    }

#define COPY_B(T, S)                                                           \
    _Pragma("unroll")                                                          \
    for (int i = 0; i < 6; ++i) {                                              \
        int idx = tid + 256 * i;                                               \
        int n = idx >> 3, wg = idx & 7;                                        \
        *(uint4*)&pool[O_B(S) + n * SA + 4 * wg] =                             \
            *(const uint4*)&g_wf[(T) * 6144 + n * 32 + 4 * wg];                \
    }

    // Prologue: stage chunk 0
    GATHER(0);
    COPY_B(0, 0);
    STS_A(0);
    __syncthreads();

    float acc[2][6][4];
#pragma unroll
    for (int p = 0; p < 2; ++p)
#pragma unroll
        for (int j = 0; j < 6; ++j)
#pragma unroll
            for (int q = 0; q < 4; ++q) acc[p][j][q] = 0.0f;

    for (int t = 0; t < NCHUNK; ++t) {
        const int s = t & 1;
        if (t + 1 < NCHUNK) {
            GATHER(t + 1);            // LDGs in flight during MMA burst
            COPY_B(t + 1, s ^ 1);     // L2-resident copy into other buffer
        }

        const unsigned aS = aLane + (unsigned)(s * NW_A * 4);
        const unsigned bS = bLane + (unsigned)(s * NW_B * 4);

        // MMA burst over 4 k16 steps of this K64 chunk
#pragma unroll
        for (int s2 = 0; s2 < 4; ++s2) {
            const unsigned ko = (unsigned)(32 * s2);   // 8 words per k16 step
            unsigned ap0[4], ap1[4], bb[12];
            LDSM4(ap0[0], ap0[1], ap0[2], ap0[3], aS + ko);
            LDSM4(ap1[0], ap1[1], ap1[2], ap1[3], aS + (unsigned)(16 * SA * 4) + ko);
            LDSM4(bb[0], bb[1], bb[2],  bb[3],  bS + ko);
            LDSM4(bb[4], bb[5], bb[6],  bb[7],  bS + (unsigned)(16 * SA * 4) + ko);
            LDSM4(bb[8], bb[9], bb[10], bb[11], bS + (unsigned)(32 * SA * 4) + ko);
#pragma unroll
            for (int j = 0; j < 6; ++j) {
                HMMA(acc[0][j], ap0[0], ap0[1], ap0[2], ap0[3], bb[2*j], bb[2*j+1]);
                HMMA(acc[1][j], ap1[0], ap1[1], ap1[2], ap1[3], bb[2*j], bb[2*j+1]);
            }
        }

        if (t + 1 < NCHUNK) STS_A(s ^ 1);
        __syncthreads();
    }

    // ---- Epilogue: bias + output + BN partials ----
    float cs[12], cq[12];
#pragma unroll
    for (int i = 0; i < 12; ++i) { cs[i] = 0.0f; cq[i] = 0.0f; }

#pragma unroll
    for (int j = 0; j < 6; ++j) {
        const int cb = wn * 48 + j * 8 + 2 * tig;
        float b0 = __ldg(&bias[cb]);
        float b1 = __ldg(&bias[cb + 1]);
#pragma unroll
        for (int p = 0; p < 2; ++p) {
            const int rb = m0 + wm * 32 + p * 16 + gid;
            const bool v0 = (rb < M_OUT);
            const bool v1 = (rb + 8 < M_OUT);
            float v00 = acc[p][j][0] + b0, v01 = acc[p][j][1] + b1;
            float v10 = acc[p][j][2] + b0, v11 = acc[p][j][3] + b1;
            if (v0) *(float2*)&out[(long long)rb * COUT + cb] = make_float2(v00, v01);
            if (v1) *(float2*)&out[(long long)(rb + 8) * COUT + cb] = make_float2(v10, v11);
            cs[2*j]   += (v0 ? v00 : 0.0f) + (v1 ? v10 : 0.0f);
            cs[2*j+1] += (v0 ? v01 : 0.0f) + (v1 ? v11 : 0.0f);
            cq[2*j]   += (v0 ? v00 * v00 : 0.0f) + (v1 ? v10 * v10 : 0.0f);
            cq[2*j+1] += (v0 ? v01 * v01 : 0.0f) + (v1 ? v11 * v11 : 0.0f);
        }
    }
    // reduce across gid (lane bits 2,3,4)
#pragma unroll
    for (int k = 4; k <= 16; k <<= 1) {
#pragma unroll
        for (int i = 0; i < 12; ++i) {
            cs[i] += __shfl_xor_sync(0xffffffffu, cs[i], k);
            cq[i] += __shfl_xor_sync(0xffffffffu, cq[i], k);
        }
    }
    if (gid == 0) {
#pragma unroll
        for (int j = 0; j < 6; ++j) {
            int col = wn * 48 + j * 8 + 2 * tig;
            RedS[wm * COUT + col]     = cs[2*j];
            RedS[wm * COUT + col + 1] = cs[2*j+1];
            RedQ[wm * COUT + col]     = cq[2*j];
            RedQ[wm * COUT + col + 1] = cq[2*j+1];
        }
    }
    __syncthreads();
    if (tid < COUT) {
        float s = RedS[tid] + RedS[COUT + tid];
        float q = RedQ[tid] + RedQ[COUT + tid];
        g_psum[tid * NBLK + bx] = s;
        g_psq[tid * NBLK + bx]  = q;
    }
}

// ---------------------------------------------------------------------------
__global__ __launch_bounds__(256) void stats_kernel(
    const float* __restrict__ gamma,
    const float* __restrict__ beta)
{
    const int c = blockIdx.x;
    const int t = threadIdx.x;
    float s = 0.0f, q = 0.0f;
    for (int b = t; b < NBLK; b += 256) {
        s += g_psum[c * NBLK + b];
        q += g_psq[c * NBLK + b];
    }
    __shared__ float ss[256], sq[256];
    ss[t] = s; sq[t] = q;
    __syncthreads();
    for (int o = 128; o > 0; o >>= 1) {
        if (t < o) { ss[t] += ss[t + o]; sq[t] += sq[t + o]; }
        __syncthreads();
    }
    if (t == 0) {
        float mean = ss[0] / (float)M_OUT;
        float var  = sq[0] / (float)M_OUT - mean * mean;
        float rs   = rsqrtf(var + BN_EPS);
        float sc   = gamma[c] * rs;
        g_scale[c] = sc;
        g_shift[c] = beta[c] - mean * sc;
    }
}

// ---------------------------------------------------------------------------
// Normalize: in-place affine; scale/shift cached in smem; 4 float4 per thread.
// Each block covers 1024 float4 items — grid divisor MUST be 1024.
// ---------------------------------------------------------------------------
#define NVEC (M_OUT * COUT / 4)   // 6,000,000
__global__ __launch_bounds__(256) void norm_kernel(float4* __restrict__ out4)
{
    __shared__ float sScale[COUT], sShift[COUT];
    if (threadIdx.x < COUT) {
        sScale[threadIdx.x] = g_scale[threadIdx.x];
        sShift[threadIdx.x] = g_shift[threadIdx.x];
    }
    __syncthreads();

    int i0 = blockIdx.x * 1024 + threadIdx.x;
#pragma unroll
    for (int u = 0; u < 4; ++u) {
        int i = i0 + u * 256;
        if (i < NVEC) {
            int c = (i % 48) * 4;
            float4 v = out4[i];
            v.x = v.x * sScale[c + 0] + sShift[c + 0];
            v.y = v.y * sScale[c + 1] + sShift[c + 1];
            v.z = v.z * sScale[c + 2] + sShift[c + 2];
            v.w = v.w * sScale[c + 3] + sShift[c + 3];
            out4[i] = v;
        }
    }
}

extern "C" void kernel_launch(void* const* d_in, const int* in_sizes, int n_in,
                              void* d_out, int out_size)
{
    const float* data    = (const float*)d_in[0];
    const float* weights = (const float*)d_in[1];
    const float* bias    = (const float*)d_in[2];
    const float* gamma   = (const float*)d_in[3];
    const float* beta    = (const float*)d_in[4];
    const void*  neigh   = (const void*)d_in[5];
    float* out = (float*)d_out;

    cudaFuncSetAttribute(conv_kernel, cudaFuncAttributeMaxDynamicSharedMemorySize,
                         POOLB);

    prep_kernel<<<NCHUNK + 1, 256>>>(weights, (const int*)neigh);
    conv_kernel<<<NBLK, 256, POOLB>>>(data, bias, neigh, out);
    stats_kernel<<<COUT, 256>>>(gamma, beta);
    norm_kernel<<<(NVEC + 1023) / 1024, 256>>>((float4*)out);
}

// round 12
// speedup vs baseline: 5.3138x; 1.1669x over previous
#include <cuda_runtime.h>
#include <cuda_fp16.h>

// Problem constants
#define M_OUT   125000
#define KNB     8
#define CIN     96
#define COUT    192
#define BM      64
#define NCHUNK  12                        // K chunks of 64 (768 total)
#define NBLK    1954                      // ceil(125000/64)
#define NBLKP   1956                      // padded to /4 for vectorized stats
#define BN_EPS  1e-5f
#define SA      36                        // smem row stride in words (conflict-free)

// Dynamic smem word offsets: A double-buffered, B double-buffered.
#define NW_A    (BM * SA)                 // 2304
#define NW_B    (COUT * SA)               // 6912
#define O_A(s)    ((s) * NW_A)                    // 0 .. 4608
#define O_B(s)    (4608 + (s) * NW_B)             // .. 18432
#define O_SROW    18432                           // 512 words
#define POOLW     18944
#define POOLB     (POOLW * 4)                     // 75776 B -> 2 CTAs/SM

// Deterministic scratch
__device__ float g_psum[COUT * NBLKP];
__device__ float g_psq [COUT * NBLKP];
__device__ float g_scale[COUT];
__device__ float g_shift[COUT];
__device__ int   g_is64;
// Pre-packed fp16 weights: [t][n][w] word = half2 over (k,k+1), k = 64t + 2w
__device__ __align__(16) unsigned g_wf[NCHUNK * COUT * 32];

#define HMMA(d, a0, a1, a2, a3, b0, b1)                                        \
    asm volatile(                                                              \
        "mma.sync.aligned.m16n8k16.row.col.f32.f16.f16.f32 "                   \
        "{%0,%1,%2,%3}, {%4,%5,%6,%7}, {%8,%9}, {%0,%1,%2,%3};"                \
        : "+f"((d)[0]), "+f"((d)[1]), "+f"((d)[2]), "+f"((d)[3])               \
        : "r"(a0), "r"(a1), "r"(a2), "r"(a3), "r"(b0), "r"(b1))

#define LDSM4(r0, r1, r2, r3, addr)                                            \
    asm volatile("ldmatrix.sync.aligned.m8n8.x4.shared.b16 {%0,%1,%2,%3}, [%4];" \
        : "=r"(r0), "=r"(r1), "=r"(r2), "=r"(r3) : "r"(addr))

#define CP_ASYNC16(dst_u32, src_ptr)                                           \
    asm volatile("cp.async.ca.shared.global [%0], [%1], 16;"                   \
        :: "r"(dst_u32), "l"(src_ptr))
#define CP_COMMIT()  asm volatile("cp.async.commit_group;" ::: "memory")
#define CP_WAIT0()   asm volatile("cp.async.wait_group 0;" ::: "memory")

// ---------------------------------------------------------------------------
// Fused prepack (blocks 0..11) + neigh dtype detect & partial-pad zero (12).
// ---------------------------------------------------------------------------
__global__ __launch_bounds__(256) void prep_kernel(const float* __restrict__ W,
                                                   const int* __restrict__ neigh32)
{
    const int t = blockIdx.x;
    if (t < NCHUNK) {
        for (int idx = threadIdx.x; idx < COUT * 32; idx += 256) {
            int n = idx >> 5, w = idx & 31;
            int k0 = t * 64 + 2 * w;
            __half2 h = __floats2half2_rn(W[k0 * COUT + n], W[(k0 + 1) * COUT + n]);
            g_wf[t * 6144 + n * 32 + w] = *reinterpret_cast<unsigned*>(&h);
        }
    } else {
        // zero the two padded partial slots per channel
        for (int idx = threadIdx.x; idx < COUT * 2; idx += 256) {
            int c = idx >> 1, p = idx & 1;
            g_psum[c * NBLKP + NBLK + p] = 0.0f;
            g_psq [c * NBLKP + NBLK + p] = 0.0f;
        }
        if (threadIdx.x == 0) {
            int is64 = 1;
            for (int i = 0; i < 256; ++i)
                if (neigh32[2 * i + 1] != 0) { is64 = 0; break; }
            g_is64 = is64;
        }
    }
}

// ---------------------------------------------------------------------------
// Conv kernel: gather-GEMM on fp16 tensor cores.
// Block = 64 rows x 192 cols, 8 warps as 2(M) x 4(N); warp tile 32x48.
// 2 CTAs/SM; B staged via cp.async (no RF round-trip), A via LDG+cvt+STS.
// ---------------------------------------------------------------------------
__global__ __launch_bounds__(256, 2) void conv_kernel(
    const float* __restrict__ data,
    const float* __restrict__ bias,
    const void* __restrict__ neigh_raw,
    float* __restrict__ out)
{
    extern __shared__ __align__(16) unsigned pool[];
    int*   sSrow = (int*)&pool[O_SROW];
    float* RedS  = (float*)pool;              // overlay after MMA: [2][192]
    float* RedQ  = RedS + 2 * COUT;

    const int tid = threadIdx.x;
    const int lid = tid & 31;
    const int wid = tid >> 5;                 // 0..7
    const int wm  = wid & 1;                  // 0..1 (M): rows wm*32..+31
    const int wn  = wid >> 1;                 // 0..3 (N): cols wn*48..+47
    const int gid = lid >> 2;                 // 0..7
    const int tig = lid & 3;                  // 0..3
    const int bx  = blockIdx.x;
    const int m0  = bx * BM;

    const int is64 = g_is64;
    const long long* n64 = (const long long*)neigh_raw;
    const int*       n32 = (const int*)neigh_raw;

    // Stage neighbor indices [64][8]
    for (int idx = tid; idx < BM * KNB; idx += 256) {
        int r  = idx >> 3;
        int kk = idx & 7;
        int m  = m0 + r;
        int srow = -1;
        if (m < M_OUT) {
            long long v = is64 ? n64[(long long)m * KNB + kk]
                               : (long long)n32[(long long)m * KNB + kk];
            if (v >= 0) srow = (int)v;
        }
        sSrow[idx] = srow;
    }
    __syncthreads();

    // ldmatrix lane-static addresses (byte offsets into pool)
    const unsigned sbase = (unsigned)__cvta_generic_to_shared(pool);
    const unsigned aLane = sbase +
        (((wm * 32 + (lid & 15)) * SA + ((lid & 16) ? 4u : 0u)) << 2);
    const unsigned bLane = sbase + ((O_B(0) +
        ((wn * 48 + ((lid >> 4) & 1) * 8 + (lid & 7)) * SA +
         ((lid & 8) ? 4u : 0u))) << 2);

    // Gather staging: 1024 float4 items -> 4 per thread. item -> (row, g)
    float4 fst[4];

#define GATHER(T)                                                              \
    _Pragma("unroll")                                                          \
    for (int i = 0; i < 4; ++i) {                                              \
        int idx = tid + 256 * i;                                               \
        int r = idx >> 4, g = idx & 15;                                        \
        int k0 = ((T) << 6) + (g << 2);                                        \
        int kk = k0 / 96, c = k0 - 96 * kk;                                    \
        int srow = sSrow[r * KNB + kk];                                        \
        fst[i] = make_float4(0.f, 0.f, 0.f, 0.f);                              \
        if (srow >= 0) fst[i] = *(const float4*)(data + srow * CIN + c);       \
    }

#define STS_A(S)                                                               \
    _Pragma("unroll")                                                          \
    for (int i = 0; i < 4; ++i) {                                              \
        int idx = tid + 256 * i;                                               \
        int r = idx >> 4, g = idx & 15;                                        \
        __half2 h01 = __floats2half2_rn(fst[i].x, fst[i].y);                   \
        __half2 h23 = __floats2half2_rn(fst[i].z, fst[i].w);                   \
        *(uint2*)&pool[O_A(S) + r * SA + 2 * g] =                              \
            make_uint2(*reinterpret_cast<unsigned*>(&h01),                     \
                       *reinterpret_cast<unsigned*>(&h23));                    \
    }

    // B copy via cp.async: 1536 16B items, 6 per thread, one commit group.
#define COPY_B_ASYNC(T, S)                                                     \
    _Pragma("unroll")                                                          \
    for (int i = 0; i < 6; ++i) {                                              \
        int idx = tid + 256 * i;                                               \
        int n = idx >> 3, wg = idx & 7;                                        \
        unsigned dst = sbase + ((unsigned)(O_B(S) + n * SA + 4 * wg) << 2);    \
        CP_ASYNC16(dst, (const void*)&g_wf[(T) * 6144 + n * 32 + 4 * wg]);     \
    }                                                                          \
    CP_COMMIT()

    // Prologue: stage chunk 0
    GATHER(0);
    COPY_B_ASYNC(0, 0);
    STS_A(0);
    CP_WAIT0();
    __syncthreads();

    float acc[2][6][4];
#pragma unroll
    for (int p = 0; p < 2; ++p)
#pragma unroll
        for (int j = 0; j < 6; ++j)
#pragma unroll
            for (int q = 0; q < 4; ++q) acc[p][j][q] = 0.0f;

    for (int t = 0; t < NCHUNK; ++t) {
        const int s = t & 1;
        if (t + 1 < NCHUNK) {
            GATHER(t + 1);                // LDGs in flight during MMA burst
            COPY_B_ASYNC(t + 1, s ^ 1);   // async B copy behind the MMAs
        }

        const unsigned aS = aLane + (unsigned)(s * NW_A * 4);
        const unsigned bS = bLane + (unsigned)(s * NW_B * 4);

        // MMA burst over 4 k16 steps of this K64 chunk
#pragma unroll
        for (int s2 = 0; s2 < 4; ++s2) {
            const unsigned ko = (unsigned)(32 * s2);   // 8 words per k16 step
            unsigned ap0[4], ap1[4], bb[12];
            LDSM4(ap0[0], ap0[1], ap0[2], ap0[3], aS + ko);
            LDSM4(ap1[0], ap1[1], ap1[2], ap1[3], aS + (unsigned)(16 * SA * 4) + ko);
            LDSM4(bb[0], bb[1], bb[2],  bb[3],  bS + ko);
            LDSM4(bb[4], bb[5], bb[6],  bb[7],  bS + (unsigned)(16 * SA * 4) + ko);
            LDSM4(bb[8], bb[9], bb[10], bb[11], bS + (unsigned)(32 * SA * 4) + ko);
#pragma unroll
            for (int j = 0; j < 6; ++j) {
                HMMA(acc[0][j], ap0[0], ap0[1], ap0[2], ap0[3], bb[2*j], bb[2*j+1]);
                HMMA(acc[1][j], ap1[0], ap1[1], ap1[2], ap1[3], bb[2*j], bb[2*j+1]);
            }
        }

        if (t + 1 < NCHUNK) STS_A(s ^ 1);
        CP_WAIT0();
        __syncthreads();
    }

    // ---- Epilogue: bias + output + BN partials ----
    float cs[12], cq[12];
#pragma unroll
    for (int i = 0; i < 12; ++i) { cs[i] = 0.0f; cq[i] = 0.0f; }

#pragma unroll
    for (int j = 0; j < 6; ++j) {
        const int cb = wn * 48 + j * 8 + 2 * tig;
        float b0 = __ldg(&bias[cb]);
        float b1 = __ldg(&bias[cb + 1]);
#pragma unroll
        for (int p = 0; p < 2; ++p) {
            const int rb = m0 + wm * 32 + p * 16 + gid;
            const bool v0 = (rb < M_OUT);
            const bool v1 = (rb + 8 < M_OUT);
            float v00 = acc[p][j][0] + b0, v01 = acc[p][j][1] + b1;
            float v10 = acc[p][j][2] + b0, v11 = acc[p][j][3] + b1;
            if (v0) *(float2*)&out[(long long)rb * COUT + cb] = make_float2(v00, v01);
            if (v1) *(float2*)&out[(long long)(rb + 8) * COUT + cb] = make_float2(v10, v11);
            cs[2*j]   += (v0 ? v00 : 0.0f) + (v1 ? v10 : 0.0f);
            cs[2*j+1] += (v0 ? v01 : 0.0f) + (v1 ? v11 : 0.0f);
            cq[2*j]   += (v0 ? v00 * v00 : 0.0f) + (v1 ? v10 * v10 : 0.0f);
            cq[2*j+1] += (v0 ? v01 * v01 : 0.0f) + (v1 ? v11 * v11 : 0.0f);
        }
    }
    // reduce across gid (lane bits 2,3,4)
#pragma unroll
    for (int k = 4; k <= 16; k <<= 1) {
#pragma unroll
        for (int i = 0; i < 12; ++i) {
            cs[i] += __shfl_xor_sync(0xffffffffu, cs[i], k);
            cq[i] += __shfl_xor_sync(0xffffffffu, cq[i], k);
        }
    }
    if (gid == 0) {
#pragma unroll
        for (int j = 0; j < 6; ++j) {
            int col = wn * 48 + j * 8 + 2 * tig;
            RedS[wm * COUT + col]     = cs[2*j];
            RedS[wm * COUT + col + 1] = cs[2*j+1];
            RedQ[wm * COUT + col]     = cq[2*j];
            RedQ[wm * COUT + col + 1] = cq[2*j+1];
        }
    }
    __syncthreads();
    if (tid < COUT) {
        float s = RedS[tid] + RedS[COUT + tid];
        float q = RedQ[tid] + RedQ[COUT + tid];
        g_psum[tid * NBLKP + bx] = s;
        g_psq[tid * NBLKP + bx]  = q;
    }
}

// ---------------------------------------------------------------------------
// Stats: float4-vectorized reduce of 1956 padded partials per channel.
// ---------------------------------------------------------------------------
__global__ __launch_bounds__(256) void stats_kernel(
    const float* __restrict__ gamma,
    const float* __restrict__ beta)
{
    const int c = blockIdx.x;
    const int t = threadIdx.x;
    const float4* ps = (const float4*)&g_psum[c * NBLKP];
    const float4* pq = (const float4*)&g_psq [c * NBLKP];
    float s = 0.0f, q = 0.0f;
    for (int b = t; b < NBLKP / 4; b += 256) {
        float4 a = ps[b], d = pq[b];
        s += (a.x + a.y) + (a.z + a.w);
        q += (d.x + d.y) + (d.z + d.w);
    }
    __shared__ float ss[256], sq[256];
    ss[t] = s; sq[t] = q;
    __syncthreads();
    for (int o = 128; o > 0; o >>= 1) {
        if (t < o) { ss[t] += ss[t + o]; sq[t] += sq[t + o]; }
        __syncthreads();
    }
    if (t == 0) {
        float mean = ss[0] / (float)M_OUT;
        float var  = sq[0] / (float)M_OUT - mean * mean;
        float rs   = rsqrtf(var + BN_EPS);
        float sc   = gamma[c] * rs;
        g_scale[c] = sc;
        g_shift[c] = beta[c] - mean * sc;
    }
}

// ---------------------------------------------------------------------------
// Normalize: in-place affine; scale/shift cached in smem; 4 float4 per thread.
// Each block covers 1024 float4 items — grid divisor MUST be 1024.
// ---------------------------------------------------------------------------
#define NVEC (M_OUT * COUT / 4)   // 6,000,000
__global__ __launch_bounds__(256) void norm_kernel(float4* __restrict__ out4)
{
    __shared__ float sScale[COUT], sShift[COUT];
    if (threadIdx.x < COUT) {
        sScale[threadIdx.x] = g_scale[threadIdx.x];
        sShift[threadIdx.x] = g_shift[threadIdx.x];
    }
    __syncthreads();

    int i0 = blockIdx.x * 1024 + threadIdx.x;
#pragma unroll
    for (int u = 0; u < 4; ++u) {
        int i = i0 + u * 256;
        if (i < NVEC) {
            int c = (i % 48) * 4;
            float4 v = out4[i];
            v.x = v.x * sScale[c + 0] + sShift[c + 0];
            v.y = v.y * sScale[c + 1] + sShift[c + 1];
            v.z = v.z * sScale[c + 2] + sShift[c + 2];
            v.w = v.w * sScale[c + 3] + sShift[c + 3];
            out4[i] = v;
        }
    }
}

extern "C" void kernel_launch(void* const* d_in, const int* in_sizes, int n_in,
                              void* d_out, int out_size)
{
    const float* data    = (const float*)d_in[0];
    const float* weights = (const float*)d_in[1];
    const float* bias    = (const float*)d_in[2];
    const float* gamma   = (const float*)d_in[3];
    const float* beta    = (const float*)d_in[4];
    const void*  neigh   = (const void*)d_in[5];
    float* out = (float*)d_out;

    cudaFuncSetAttribute(conv_kernel, cudaFuncAttributeMaxDynamicSharedMemorySize,
                         POOLB);

    prep_kernel<<<NCHUNK + 1, 256>>>(weights, (const int*)neigh);
    conv_kernel<<<NBLK, 256, POOLB>>>(data, bias, neigh, out);
    stats_kernel<<<COUT, 256>>>(gamma, beta);
    norm_kernel<<<(NVEC + 1023) / 1024, 256>>>((float4*)out);
}